// round 13
// baseline (speedup 1.0000x reference)
#include <cuda_runtime.h>
#include <cuda_fp16.h>
#include <cstdint>
#include <cstddef>

#define B_ 16
#define LK_ 8192
#define D_ 1024
#define H_ 1024
#define M_TOTAL (B_*LK_)

#define TM 128             // CTA rows
#define TN 128             // h-chunk width
#define NCH (H_/TN)        // 8
#define NGH 512            // total k16 groups = 64 k16 x 8 nc

// ---- device scratch ----
__device__ float g_qp[B_*H_];
// keys fp16 A-fragment images: [mtile(1024)][k16(64)][r16(8)][lane(32)] x 16B
__device__ __half g_keysH[(size_t)M_TOTAL * D_];          // 256 MB
// W_k fp16 B-fragment images: [gh(512)=nc*64+k16][ndt(8)][lane(32)] x 16B
__device__ __half g_WkH[(size_t)D_ * H_];                 // 2 MB

// ---------------- helpers ----------------
__device__ __forceinline__ float tanh_hw(float x) {
    float r; asm("tanh.approx.f32 %0, %1;" : "=f"(r) : "f"(x)); return r;
}
__device__ __forceinline__ uint32_t h2u(__half2 h) {
    return *reinterpret_cast<uint32_t*>(&h);
}
__device__ __forceinline__ void mmaf16(float* c, uint4 a, uint32_t b0, uint32_t b1) {
    asm volatile(
        "mma.sync.aligned.m16n8k16.row.col.f32.f16.f16.f32 "
        "{%0,%1,%2,%3},{%4,%5,%6,%7},{%8,%9},{%0,%1,%2,%3};"
        : "+f"(c[0]), "+f"(c[1]), "+f"(c[2]), "+f"(c[3])
        : "r"(a.x), "r"(a.y), "r"(a.z), "r"(a.w), "r"(b0), "r"(b1));
}

// ---------------- prep: keys -> fp16 A-fragment images ----------------
__global__ __launch_bounds__(256) void prep_keys(const float* __restrict__ keys) {
    int u = blockIdx.x * 256 + threadIdx.x;      // 16,777,216 units
    int lane = u & 31;
    int r16  = (u >> 5) & 7;
    int k16  = (u >> 8) & 63;
    int mtile = u >> 14;
    int g = lane >> 2, t = lane & 3;
    const float* src = keys + ((size_t)(mtile * 128 + r16 * 16 + g)) * D_ + k16 * 16;
    float2 f00 = *(const float2*)(src + 2 * t);
    float2 f01 = *(const float2*)(src + 2 * t + 8);
    float2 f10 = *(const float2*)(src + 8 * D_ + 2 * t);
    float2 f11 = *(const float2*)(src + 8 * D_ + 2 * t + 8);
    uint4 v;
    v.x = h2u(__float22half2_rn(f00));
    v.y = h2u(__float22half2_rn(f10));
    v.z = h2u(__float22half2_rn(f01));
    v.w = h2u(__float22half2_rn(f11));
    ((uint4*)g_keysH)[u] = v;
}

// ---------------- prep: W_k -> fp16 B-fragment images ----------------
__global__ __launch_bounds__(256) void prep_wk(const float* __restrict__ Wk) {
    int u = blockIdx.x * 256 + threadIdx.x;      // 131,072 units
    int lane = u & 31;
    int ndt  = (u >> 5) & 7;
    int k16  = (u >> 8) & 63;
    int nc   = u >> 14;
    int g = lane >> 2, t = lane & 3;
    int h  = nc * 128 + ndt * 16 + g;
    int k0 = k16 * 16 + 2 * t;
    float2 f00 = make_float2(Wk[(size_t)k0 * H_ + h],       Wk[(size_t)(k0 + 1) * H_ + h]);
    float2 f01 = make_float2(Wk[(size_t)(k0 + 8) * H_ + h], Wk[(size_t)(k0 + 9) * H_ + h]);
    float2 f10 = make_float2(Wk[(size_t)k0 * H_ + h + 8],   Wk[(size_t)(k0 + 1) * H_ + h + 8]);
    float2 f11 = make_float2(Wk[(size_t)(k0 + 8) * H_ + h + 8], Wk[(size_t)(k0 + 9) * H_ + h + 8]);
    uint4 v;
    v.x = h2u(__float22half2_rn(f00));
    v.y = h2u(__float22half2_rn(f01));
    v.z = h2u(__float22half2_rn(f10));
    v.w = h2u(__float22half2_rn(f11));
    ((uint4*)g_WkH)[u] = v;
}

// ---------------- qp[b,h] = queries @ W_q (split-D x4, fp32) ----------------
__global__ __launch_bounds__(256) void qproj_kernel(const float* __restrict__ q,
                                                    const float* __restrict__ Wq) {
    int b = blockIdx.y;
    int h = blockIdx.x * 64 + (threadIdx.x >> 2);
    int part = threadIdx.x & 3;
    const float* qr = q + b * D_;
    float acc = 0.f;
    int d0 = part * 256;
#pragma unroll 8
    for (int d = d0; d < d0 + 256; ++d) acc = fmaf(qr[d], Wq[(size_t)d * H_ + h], acc);
    acc += __shfl_xor_sync(0xffffffffu, acc, 1);
    acc += __shfl_xor_sync(0xffffffffu, acc, 2);
    if (part == 0) g_qp[b * H_ + h] = acc;
}

// ---------------- fused keys@W_k -> tanh -> dot(w_v), global-direct fp16 tensor ----------------
__global__ void __launch_bounds__(256, 2) attn_kernel(const float* __restrict__ wv,
                                                      float* __restrict__ out) {
    __shared__ float s_qp[TN];
    __shared__ float s_wv[TN];
    __shared__ float s_red[TM * 4];

    const int tid  = threadIdx.x;
    const int lane = tid & 31, warp = tid >> 5;
    const int wm = warp >> 2, wn = warp & 3;        // 2(m) x 4(n) grid, warp tile 64x32
    const int g = lane >> 2, t = lane & 3;
    const int mtile = blockIdx.x;
    const int m_base = mtile * TM;
    const int b = mtile >> 6;                        // 64 tiles per batch

    // fragment-image base pointers (uint4 units)
    const uint4* __restrict__ Abase =
        ((const uint4*)g_keysH) + (size_t)mtile * 16384 + (size_t)(wm * 4) * 32 + lane;
    const uint4* __restrict__ Bbase =
        ((const uint4*)g_WkH) + (size_t)(wn * 2) * 32 + lane;

    float score = 0.f;
    if (tid < TN) { s_qp[tid] = g_qp[b * H_ + tid]; s_wv[tid] = wv[tid]; }
    __syncthreads();

    // register double buffers
    uint4 A0[4], A1[4], B0[2], B1[2];
#pragma unroll
    for (int mi = 0; mi < 4; ++mi) A0[mi] = __ldg(Abase + mi * 32);            // k16=0
    B0[0] = __ldg(Bbase);       B0[1] = __ldg(Bbase + 32);                     // gh=0
#pragma unroll
    for (int mi = 0; mi < 4; ++mi) A1[mi] = __ldg(Abase + 256 + mi * 32);      // k16=1
    B1[0] = __ldg(Bbase + 256); B1[1] = __ldg(Bbase + 288);                    // gh=1

    float acc[4][2][2][4];
#pragma unroll
    for (int mi = 0; mi < 4; ++mi)
#pragma unroll
        for (int dt = 0; dt < 2; ++dt)
#pragma unroll
            for (int nj = 0; nj < 2; ++nj)
#pragma unroll
                for (int r = 0; r < 4; ++r) acc[mi][dt][nj][r] = 0.f;

    auto step = [&](int gh, uint4* A, uint4* Bv) {
#pragma unroll
        for (int mi = 0; mi < 4; ++mi) {
            mmaf16(acc[mi][0][0], A[mi], Bv[0].x, Bv[0].y);
            mmaf16(acc[mi][0][1], A[mi], Bv[0].z, Bv[0].w);
            mmaf16(acc[mi][1][0], A[mi], Bv[1].x, Bv[1].y);
            mmaf16(acc[mi][1][1], A[mi], Bv[1].z, Bv[1].w);
        }
        int gh2 = gh + 2; if (gh2 > NGH - 1) gh2 = NGH - 1;
        const uint4* ap = Abase + (size_t)(gh2 & 63) * 256;
#pragma unroll
        for (int mi = 0; mi < 4; ++mi) A[mi] = __ldg(ap + mi * 32);
        const uint4* bp = Bbase + (size_t)gh2 * 256;
        Bv[0] = __ldg(bp); Bv[1] = __ldg(bp + 32);
    };

    auto epilogue = [&](int nc) {
#pragma unroll
        for (int mi = 0; mi < 4; ++mi) {
            float p0 = 0.f, p1 = 0.f;
#pragma unroll
            for (int dt = 0; dt < 2; ++dt)
#pragma unroll
                for (int nj = 0; nj < 2; ++nj) {
                    int c0 = wn * 32 + dt * 16 + nj * 8 + 2 * t;
                    float q0 = s_qp[c0], q1 = s_qp[c0 + 1];
                    float w0 = s_wv[c0], w1 = s_wv[c0 + 1];
                    float* a = acc[mi][dt][nj];
                    p0 += tanh_hw(q0 + a[0]) * w0 + tanh_hw(q1 + a[1]) * w1;
                    p1 += tanh_hw(q0 + a[2]) * w0 + tanh_hw(q1 + a[3]) * w1;
                    a[0] = 0.f; a[1] = 0.f; a[2] = 0.f; a[3] = 0.f;
                }
            p0 += __shfl_xor_sync(0xffffffffu, p0, 1);
            p0 += __shfl_xor_sync(0xffffffffu, p0, 2);
            p1 += __shfl_xor_sync(0xffffffffu, p1, 1);
            p1 += __shfl_xor_sync(0xffffffffu, p1, 2);
            if (t == 0) {
                int r0 = wm * 64 + mi * 16 + g;
                s_red[(r0    ) * 4 + wn] = p0;
                s_red[(r0 + 8) * 4 + wn] = p1;
            }
        }
        __syncthreads();   // s_red ready; all tanh s_qp/s_wv reads done
        if (tid < TM)
            score += s_red[tid * 4 + 0] + s_red[tid * 4 + 1]
                   + s_red[tid * 4 + 2] + s_red[tid * 4 + 3];
        if (nc + 1 < NCH && tid < TN) {
            s_qp[tid] = g_qp[b * H_ + (nc + 1) * TN + tid];
            s_wv[tid] = wv[(nc + 1) * TN + tid];
        }
        __syncthreads();   // s_qp/s_wv update + s_red reads complete before reuse
    };

    for (int gh = 0; gh < NGH; gh += 2) {
        step(gh, A0, B0);
        step(gh + 1, A1, B1);
        if (((gh + 1) & 63) == 63) epilogue((gh + 1) >> 6);
    }

    if (tid < TM) out[m_base + tid] = score;
}

// ---------------- launch ----------------
extern "C" void kernel_launch(void* const* d_in, const int* in_sizes, int n_in,
                              void* d_out, int out_size) {
    (void)in_sizes; (void)n_in; (void)out_size;
    const float* queries = (const float*)d_in[0];   // [16,1,1024]
    const float* keys    = (const float*)d_in[1];   // [16,8192,1024]
    const float* Wq      = (const float*)d_in[2];   // [1024,1024]
    const float* Wk      = (const float*)d_in[3];   // [1024,1024]
    const float* wv      = (const float*)d_in[4];   // [1024,1]
    float* out = (float*)d_out;                     // [16,8192]

    prep_keys<<<65536, 256>>>(keys);
    prep_wk<<<512, 256>>>(Wk);
    qproj_kernel<<<dim3(H_ / 64, B_), 256>>>(queries, Wq);
    attn_kernel<<<M_TOTAL / TM, 256>>>(wv, out);
}

// round 15
// speedup vs baseline: 1.2229x; 1.2229x over previous
#include <cuda_runtime.h>
#include <cuda_fp16.h>
#include <cstdint>
#include <cstddef>

#define B_ 16
#define LK_ 8192
#define D_ 1024
#define H_ 1024
#define M_TOTAL (B_*LK_)

#define TM 128             // CTA rows
#define TN 128             // h-chunk width
#define NCH_CTA 4          // h-chunks per CTA (half of 8)
#define TOTS 64            // stages per CTA (4 nc x 16 k-stages)
#define NSTAGE 4
#define A_STG_BYTES 16384  // 4 k16 x 8 r16 x 32 lane x 16B

// smem byte offsets
#define SM_A   0
#define SM_QP  (NSTAGE*A_STG_BYTES)       // 65536
#define SM_WV  (SM_QP + TN*4)
#define SM_RED (SM_WV + TN*4)
#define SMEM_BYTES (SM_RED + TM*4*4)      // 68608

// ---- device scratch ----
__device__ float g_qp[B_*H_];
__device__ float g_part[2 * M_TOTAL];                     // per-half partial scores
// keys fp16 A-fragment images: [mtile(1024)][k16(64)][r16(8)][lane(32)] x 16B
__device__ __half g_keysH[(size_t)M_TOTAL * D_];          // 256 MB
// W_k fp16 B-fragment images: [gh(512)=nc*64+k16][ndt(8)][lane(32)] x 16B
__device__ __half g_WkH[(size_t)D_ * H_];                 // 2 MB

// ---------------- helpers ----------------
__device__ __forceinline__ float tanh_hw(float x) {
    float r; asm("tanh.approx.f32 %0, %1;" : "=f"(r) : "f"(x)); return r;
}
__device__ __forceinline__ void cp16(void* dst, const void* src) {
    uint32_t d = (uint32_t)__cvta_generic_to_shared(dst);
    asm volatile("cp.async.cg.shared.global [%0], [%1], 16;\n" :: "r"(d), "l"(src));
}
__device__ __forceinline__ uint32_t h2u(__half2 h) {
    return *reinterpret_cast<uint32_t*>(&h);
}
__device__ __forceinline__ void mmaf16(float* c, uint4 a, uint32_t b0, uint32_t b1) {
    asm volatile(
        "mma.sync.aligned.m16n8k16.row.col.f32.f16.f16.f32 "
        "{%0,%1,%2,%3},{%4,%5,%6,%7},{%8,%9},{%0,%1,%2,%3};"
        : "+f"(c[0]), "+f"(c[1]), "+f"(c[2]), "+f"(c[3])
        : "r"(a.x), "r"(a.y), "r"(a.z), "r"(a.w), "r"(b0), "r"(b1));
}

// ---------------- prep: keys -> fp16 A-fragment images ----------------
__global__ __launch_bounds__(256) void prep_keys(const float* __restrict__ keys) {
    int u = blockIdx.x * 256 + threadIdx.x;      // 16,777,216 units
    int lane = u & 31;
    int r16  = (u >> 5) & 7;
    int k16  = (u >> 8) & 63;
    int mtile = u >> 14;
    int g = lane >> 2, t = lane & 3;
    const float* src = keys + ((size_t)(mtile * 128 + r16 * 16 + g)) * D_ + k16 * 16;
    float2 f00 = *(const float2*)(src + 2 * t);
    float2 f01 = *(const float2*)(src + 2 * t + 8);
    float2 f10 = *(const float2*)(src + 8 * D_ + 2 * t);
    float2 f11 = *(const float2*)(src + 8 * D_ + 2 * t + 8);
    uint4 v;
    v.x = h2u(__float22half2_rn(f00));
    v.y = h2u(__float22half2_rn(f10));
    v.z = h2u(__float22half2_rn(f01));
    v.w = h2u(__float22half2_rn(f11));
    ((uint4*)g_keysH)[u] = v;
}

// ---------------- prep: W_k -> fp16 B-fragment images ----------------
__global__ __launch_bounds__(256) void prep_wk(const float* __restrict__ Wk) {
    int u = blockIdx.x * 256 + threadIdx.x;      // 131,072 units
    int lane = u & 31;
    int ndt  = (u >> 5) & 7;
    int k16  = (u >> 8) & 63;
    int nc   = u >> 14;
    int g = lane >> 2, t = lane & 3;
    int h  = nc * 128 + ndt * 16 + g;
    int k0 = k16 * 16 + 2 * t;
    float2 f00 = make_float2(Wk[(size_t)k0 * H_ + h],       Wk[(size_t)(k0 + 1) * H_ + h]);
    float2 f01 = make_float2(Wk[(size_t)(k0 + 8) * H_ + h], Wk[(size_t)(k0 + 9) * H_ + h]);
    float2 f10 = make_float2(Wk[(size_t)k0 * H_ + h + 8],   Wk[(size_t)(k0 + 1) * H_ + h + 8]);
    float2 f11 = make_float2(Wk[(size_t)(k0 + 8) * H_ + h + 8], Wk[(size_t)(k0 + 9) * H_ + h + 8]);
    uint4 v;
    v.x = h2u(__float22half2_rn(f00));
    v.y = h2u(__float22half2_rn(f01));
    v.z = h2u(__float22half2_rn(f10));
    v.w = h2u(__float22half2_rn(f11));
    ((uint4*)g_WkH)[u] = v;
}

// ---------------- qp[b,h] = queries @ W_q (split-D x4, fp32) ----------------
__global__ __launch_bounds__(256) void qproj_kernel(const float* __restrict__ q,
                                                    const float* __restrict__ Wq) {
    int b = blockIdx.y;
    int h = blockIdx.x * 64 + (threadIdx.x >> 2);
    int part = threadIdx.x & 3;
    const float* qr = q + b * D_;
    float acc = 0.f;
    int d0 = part * 256;
#pragma unroll 8
    for (int d = d0; d < d0 + 256; ++d) acc = fmaf(qr[d], Wq[(size_t)d * H_ + h], acc);
    acc += __shfl_xor_sync(0xffffffffu, acc, 1);
    acc += __shfl_xor_sync(0xffffffffu, acc, 2);
    if (part == 0) g_qp[b * H_ + h] = acc;
}

// ---------------- final reduce: out[m] = part[0][m] + part[1][m] ----------------
__global__ __launch_bounds__(256) void reduce_kernel(float* __restrict__ out) {
    int m = blockIdx.x * 256 + threadIdx.x;
    out[m] = g_part[m] + g_part[M_TOTAL + m];
}

// A-only stage fill: 16KB = 4 cp16/thread (k16 index identical for both halves)
__device__ __forceinline__ void load_stageA(char* smem, int mtile, int sn, int slot, int tid) {
    const __half* srcA = g_keysH + ((size_t)mtile * 64 + (size_t)(sn & 15) * 4) * 2048;
    __half* dA = (__half*)(smem + SM_A + slot * A_STG_BYTES);
#pragma unroll
    for (int i = 0; i < 4; ++i)
        cp16(dA + (tid + i * 256) * 8, srcA + (tid + i * 256) * 8);
}

// ---------------- fused keys@W_k -> tanh -> dot(w_v), fp16 tensor, split-H ----------------
__global__ void __launch_bounds__(256, 2) attn_kernel(const float* __restrict__ wv,
                                                      float* __restrict__ outp) {
    extern __shared__ char smem[];
    float* s_qp  = (float*)(smem + SM_QP);
    float* s_wv  = (float*)(smem + SM_WV);
    float* s_red = (float*)(smem + SM_RED);

    const int tid  = threadIdx.x;
    const int lane = tid & 31, warp = tid >> 5;
    const int wm = warp >> 2, wn = warp & 3;        // 2(m) x 4(n) grid, warp tile 64x32
    const int g = lane >> 2, t = lane & 3;
    const int mtile = blockIdx.x >> 1;
    const int half  = blockIdx.x & 1;
    const int m_base = mtile * TM;
    const int b = mtile >> 6;                        // 64 tiles per batch
    const int nc0 = half * NCH_CTA;                  // first h-chunk of this CTA
    const int ghbase = half * 256;                   // first k16-group (global)

    // B fragment-image pointer for this CTA's h-range (uint4 units)
    const uint4* __restrict__ WkB =
        ((const uint4*)g_WkH) + (size_t)ghbase * 256 + (size_t)wn * 2 * 32 + lane;

    float score = 0.f;
    if (tid < TN) { s_qp[tid] = g_qp[b * H_ + nc0 * TN + tid]; s_wv[tid] = wv[nc0 * TN + tid]; }

    // A pipeline prologue: stages 0..2
    load_stageA(smem, mtile, 0, 0, tid);
    asm volatile("cp.async.commit_group;\n");
    load_stageA(smem, mtile, 1, 1, tid);
    asm volatile("cp.async.commit_group;\n");
    load_stageA(smem, mtile, 2, 2, tid);
    asm volatile("cp.async.commit_group;\n");

    // B register prologue: local groups 0 (current) and 1 (next)
    uint4 Bc0 = __ldg(WkB);
    uint4 Bc1 = __ldg(WkB + 32);
    uint4 Bn0 = __ldg(WkB + 256);
    uint4 Bn1 = __ldg(WkB + 288);

    float acc[4][2][2][4];
#pragma unroll
    for (int mi = 0; mi < 4; ++mi)
#pragma unroll
        for (int dt = 0; dt < 2; ++dt)
#pragma unroll
            for (int nj = 0; nj < 2; ++nj)
#pragma unroll
                for (int r = 0; r < 4; ++r) acc[mi][dt][nj][r] = 0.f;

    int slot = 0;                  // slot of current stage
    int slot_nx = NSTAGE - 1;      // slot receiving stage s+NSTAGE-1

    for (int s = 0; s < TOTS; ++s) {
        asm volatile("cp.async.wait_group %0;\n" :: "n"(NSTAGE - 2));
        __syncthreads();
        if (s + NSTAGE - 1 < TOTS) load_stageA(smem, mtile, s + NSTAGE - 1, slot_nx, tid);
        asm volatile("cp.async.commit_group;\n");

        const char* sA = smem + SM_A + slot * A_STG_BYTES;

#pragma unroll
        for (int h = 0; h < 4; ++h) {
            uint4 bA = Bc0, bB = Bc1;
            Bc0 = Bn0; Bc1 = Bn1;
            int ghl2 = s * 4 + h + 2;
            if (ghl2 > 255) ghl2 = 255;
            const uint4* bp = WkB + (size_t)ghl2 * 256;
            Bn0 = __ldg(bp);
            Bn1 = __ldg(bp + 32);
#pragma unroll
            for (int mi = 0; mi < 4; ++mi) {
                uint4 a = *(const uint4*)(sA + (h * 8 + wm * 4 + mi) * 512 + lane * 16);
                mmaf16(acc[mi][0][0], a, bA.x, bA.y);
                mmaf16(acc[mi][0][1], a, bA.z, bA.w);
                mmaf16(acc[mi][1][0], a, bB.x, bB.y);
                mmaf16(acc[mi][1][1], a, bB.z, bB.w);
            }
        }

        if ((s & 15) == 15) {
            const int ncl = s >> 4;                  // local chunk 0..3
#pragma unroll
            for (int mi = 0; mi < 4; ++mi) {
                float p0 = 0.f, p1 = 0.f;
#pragma unroll
                for (int dt = 0; dt < 2; ++dt)
#pragma unroll
                    for (int nj = 0; nj < 2; ++nj) {
                        int c0 = wn * 32 + dt * 16 + nj * 8 + 2 * t;
                        float q0 = s_qp[c0], q1 = s_qp[c0 + 1];
                        float w0 = s_wv[c0], w1 = s_wv[c0 + 1];
                        float* a = acc[mi][dt][nj];
                        p0 += tanh_hw(q0 + a[0]) * w0 + tanh_hw(q1 + a[1]) * w1;
                        p1 += tanh_hw(q0 + a[2]) * w0 + tanh_hw(q1 + a[3]) * w1;
                        a[0] = 0.f; a[1] = 0.f; a[2] = 0.f; a[3] = 0.f;
                    }
                p0 += __shfl_xor_sync(0xffffffffu, p0, 1);
                p0 += __shfl_xor_sync(0xffffffffu, p0, 2);
                p1 += __shfl_xor_sync(0xffffffffu, p1, 1);
                p1 += __shfl_xor_sync(0xffffffffu, p1, 2);
                if (t == 0) {
                    int r0 = wm * 64 + mi * 16 + g;
                    s_red[(r0    ) * 4 + wn] = p0;
                    s_red[(r0 + 8) * 4 + wn] = p1;
                }
            }
            __syncthreads();   // s_red ready; also fences s_qp/s_wv reads above
            if (tid < TM)
                score += s_red[tid * 4 + 0] + s_red[tid * 4 + 1]
                       + s_red[tid * 4 + 2] + s_red[tid * 4 + 3];
            if (ncl + 1 < NCH_CTA && tid < TN) {
                int ncn = nc0 + ncl + 1;
                s_qp[tid] = g_qp[b * H_ + ncn * TN + tid];
                s_wv[tid] = wv[ncn * TN + tid];
            }
            // next-iteration top __syncthreads orders these writes vs readers
        }

        slot = (slot == NSTAGE - 1) ? 0 : slot + 1;
        slot_nx = (slot_nx == NSTAGE - 1) ? 0 : slot_nx + 1;
    }

    asm volatile("cp.async.wait_group 0;\n");
    if (tid < TM) outp[half * M_TOTAL + m_base + tid] = score;
}

// ---------------- launch ----------------
extern "C" void kernel_launch(void* const* d_in, const int* in_sizes, int n_in,
                              void* d_out, int out_size) {
    (void)in_sizes; (void)n_in; (void)out_size;
    const float* queries = (const float*)d_in[0];   // [16,1,1024]
    const float* keys    = (const float*)d_in[1];   // [16,8192,1024]
    const float* Wq      = (const float*)d_in[2];   // [1024,1024]
    const float* Wk      = (const float*)d_in[3];   // [1024,1024]
    const float* wv      = (const float*)d_in[4];   // [1024,1]
    float* out = (float*)d_out;                     // [16,8192]

    cudaFuncSetAttribute(attn_kernel, cudaFuncAttributeMaxDynamicSharedMemorySize, SMEM_BYTES);

    float* d_part = nullptr;
    cudaGetSymbolAddress((void**)&d_part, g_part);

    prep_keys<<<65536, 256>>>(keys);
    prep_wk<<<512, 256>>>(Wk);
    qproj_kernel<<<dim3(H_ / 64, B_), 256>>>(queries, Wq);
    attn_kernel<<<2 * (M_TOTAL / TM), 256, SMEM_BYTES>>>(wv, d_part);
    reduce_kernel<<<M_TOTAL / 256, 256>>>(out);
}